// round 6
// baseline (speedup 1.0000x reference)
#include <cuda_runtime.h>
#include <cuda_bf16.h>
#include <cstdint>

// ============================================================================
// out = chain of 20 Linear(64,64) over x[524288,64], fp32.
// Chain is affine (no nonlinearity) => compose 20 maps into ONE (Mc, c):
// out = x @ Mc^T + c.
//   Kernel 1: single-launch tree composition (10 CTAs, cross-CTA flags),
//             each 64x64x64 compose done with mma.sync bf16x4.
//   Kernel 2: apply via mma.sync m16n8k16 bf16x3, 256 rows per CTA.
// Base sm_103 target (no tcgen05 in this build pipeline).
// ============================================================================

#define N_TOK   524288
#define DIM     64
#define ROWS_PER_CTA 256

// ---------------------------------------------------------------------------
// Global buffers + flags (zero-init at load; flags self-reset every launch)
// ---------------------------------------------------------------------------
struct AffineMap {
    float M[DIM * DIM];  // out_j = sum_k M[j][k] * in_k + c[j]
    float c[DIM];
};

__device__ AffineMap g_P[10];   // level 0: pairs of raw layers
__device__ AffineMap g_Q[5];    // level 1
__device__ AffineMap g_R[2];    // level 2 (layers 0..7, 8..15)
__device__ AffineMap g_S;       // layers 0..15
__device__ AffineMap g_final;   // layers 0..19
__device__ int g_f0[10];
__device__ int g_f1[5];
__device__ int g_f2;            // R1 ready

// ---------------------------------------------------------------------------
// bf16 split + mma.sync helpers
// ---------------------------------------------------------------------------
__device__ __forceinline__ void split2(float2 v, uint32_t& hi, uint32_t& lo) {
    __nv_bfloat16 hx = __float2bfloat16_rn(v.x);
    __nv_bfloat16 hy = __float2bfloat16_rn(v.y);
    __nv_bfloat16 lx = __float2bfloat16_rn(v.x - __bfloat162float(hx));
    __nv_bfloat16 ly = __float2bfloat16_rn(v.y - __bfloat162float(hy));
    hi = (uint32_t)__bfloat16_as_ushort(hx) |
         ((uint32_t)__bfloat16_as_ushort(hy) << 16);
    lo = (uint32_t)__bfloat16_as_ushort(lx) |
         ((uint32_t)__bfloat16_as_ushort(ly) << 16);
}

__device__ __forceinline__ void mma16816(float* c, const uint32_t* a,
                                         const uint32_t* b) {
    asm volatile(
        "mma.sync.aligned.m16n8k16.row.col.f32.bf16.bf16.f32 "
        "{%0,%1,%2,%3}, {%4,%5,%6,%7}, {%8,%9}, {%0,%1,%2,%3};\n"
        : "+f"(c[0]), "+f"(c[1]), "+f"(c[2]), "+f"(c[3])
        : "r"(a[0]), "r"(a[1]), "r"(a[2]), "r"(a[3]), "r"(b[0]), "r"(b[1]));
}

// ---------------------------------------------------------------------------
// Cross-CTA flags. Producer: all threads store -> __syncthreads() ->
// tid0 {__threadfence(); atomicExch(f,1)}  (release chain via bar.sync hb).
// Consumer: tid0 polls + resets -> __syncthreads() -> __threadfence().
// ---------------------------------------------------------------------------
__device__ __forceinline__ void flag_set(int* f) {
    __threadfence();
    atomicExch(f, 1);
}
__device__ __forceinline__ void flag_wait_reset(int* f) {
    while (atomicAdd(f, 0) == 0) {}
    atomicExch(f, 0);
}

// ---------------------------------------------------------------------------
// One 64x64x64 affine compose on a 256-thread CTA via mma.sync bf16x4.
// dstM = Mb @ Ma (Ma applied first); dstc = Mb @ ca + cb.
// All input loads use __ldcg (data may be produced in this same launch; L2 is
// the coherence point for the flag protocol).
// Fragment layout identical to the validated apply kernel:
//   warp (w>>1, w&1) -> 16-row x 32-col block of dst.
//   A[m][t] = Mb[m][t] (row-contiguous); B[n][t] = Ma[t][n] (strided gather).
// ---------------------------------------------------------------------------
__device__ void compose_mma(const float* __restrict__ Ma,
                            const float* __restrict__ ca,
                            const float* __restrict__ Mb,
                            const float* __restrict__ cb,
                            float* __restrict__ dstM,
                            float* __restrict__ dstc) {
    const int tid  = threadIdx.x;
    const int lane = tid & 31;
    const int w    = tid >> 5;
    const int g    = lane >> 2;
    const int tig  = lane & 3;
    const int warp_r = (w >> 1) * 16;   // dst row block
    const int warp_c = (w & 1) * 32;    // dst col block

    // B fragments: B[n][t] = Ma[t][n]
    uint32_t bhi[4][4][2], blo[4][4][2];
#pragma unroll
    for (int kt = 0; kt < 4; kt++)
#pragma unroll
        for (int nt = 0; nt < 4; nt++) {
            int n  = warp_c + nt * 8 + g;
            int t0 = kt * 16 + 2 * tig;
            float2 p0 = make_float2(__ldcg(Ma + (t0 + 0) * DIM + n),
                                    __ldcg(Ma + (t0 + 1) * DIM + n));
            float2 p1 = make_float2(__ldcg(Ma + (t0 + 8) * DIM + n),
                                    __ldcg(Ma + (t0 + 9) * DIM + n));
            split2(p0, bhi[kt][nt][0], blo[kt][nt][0]);
            split2(p1, bhi[kt][nt][1], blo[kt][nt][1]);
        }

    // A fragments from Mb rows + MMA (4 terms: hh, hl, lh, ll)
    const float* ar = Mb + (size_t)(warp_r + g) * DIM;
    float acc[4][4] = {};
#pragma unroll
    for (int kt = 0; kt < 4; kt++) {
        int t0 = kt * 16 + 2 * tig;
        float2 a00 = __ldcg(reinterpret_cast<const float2*>(ar + t0));
        float2 a10 = __ldcg(reinterpret_cast<const float2*>(ar + 8 * DIM + t0));
        float2 a01 = __ldcg(reinterpret_cast<const float2*>(ar + t0 + 8));
        float2 a11 = __ldcg(reinterpret_cast<const float2*>(ar + 8 * DIM + t0 + 8));
        uint32_t ahi[4], alo[4];
        split2(a00, ahi[0], alo[0]);
        split2(a10, ahi[1], alo[1]);
        split2(a01, ahi[2], alo[2]);
        split2(a11, ahi[3], alo[3]);
#pragma unroll
        for (int nt = 0; nt < 4; nt++) {
            mma16816(acc[nt], ahi, bhi[kt][nt]);
            mma16816(acc[nt], ahi, blo[kt][nt]);
            mma16816(acc[nt], alo, bhi[kt][nt]);
            mma16816(acc[nt], alo, blo[kt][nt]);
        }
    }

    // Store dst
#pragma unroll
    for (int nt = 0; nt < 4; nt++) {
        int col = warp_c + nt * 8 + 2 * tig;
        int row = warp_r + g;
        *reinterpret_cast<float2*>(dstM + (size_t)row * DIM + col) =
            make_float2(acc[nt][0], acc[nt][1]);
        *reinterpret_cast<float2*>(dstM + (size_t)(row + 8) * DIM + col) =
            make_float2(acc[nt][2], acc[nt][3]);
    }

    // Bias: dstc[j] = cb[j] + sum_t Mb[j][t] * ca[t]  (fp32)
    if (tid < DIM) {
        int j = tid;
        float s = __ldcg(cb + j);
#pragma unroll 8
        for (int t = 0; t < DIM; t++)
            s += __ldcg(Mb + j * DIM + t) * __ldcg(ca + t);
        dstc[j] = s;
    }
}

// ---------------------------------------------------------------------------
// Fused tree composition, single launch, 10 CTAs x 256 threads.
// Level 0: CTA i -> P[i] = L(2i+1) o L(2i)
// Level 1: CTA i<5 -> Q[i] = P[2i+1] o P[2i]
// Level 2: CTA 0 -> R0 = Q1 o Q0 ; CTA 1 -> R1 = Q3 o Q2
// Level 3: CTA 0 -> S = R1 o R0
// Level 4: CTA 0 -> final = Q4 o S
// Every flag is set once and reset once per launch (replay-safe).
// ---------------------------------------------------------------------------
__global__ void __launch_bounds__(256)
compose_kernel(const float* __restrict__ W, const float* __restrict__ bb) {
    const int cta = blockIdx.x;
    const int tid = threadIdx.x;

    compose_mma(W + (size_t)(2 * cta) * DIM * DIM, bb + (2 * cta) * DIM,
                W + (size_t)(2 * cta + 1) * DIM * DIM, bb + (2 * cta + 1) * DIM,
                g_P[cta].M, g_P[cta].c);
    __syncthreads();
    if (tid == 0) flag_set(&g_f0[cta]);

    if (cta < 5) {
        if (tid == 0) {
            flag_wait_reset(&g_f0[2 * cta]);
            flag_wait_reset(&g_f0[2 * cta + 1]);
        }
        __syncthreads();
        __threadfence();
        compose_mma(g_P[2 * cta].M, g_P[2 * cta].c,
                    g_P[2 * cta + 1].M, g_P[2 * cta + 1].c,
                    g_Q[cta].M, g_Q[cta].c);
        __syncthreads();
        if (tid == 0) flag_set(&g_f1[cta]);
    }

    if (cta < 2) {
        if (tid == 0) {
            flag_wait_reset(&g_f1[2 * cta]);
            flag_wait_reset(&g_f1[2 * cta + 1]);
        }
        __syncthreads();
        __threadfence();
        compose_mma(g_Q[2 * cta].M, g_Q[2 * cta].c,
                    g_Q[2 * cta + 1].M, g_Q[2 * cta + 1].c,
                    g_R[cta].M, g_R[cta].c);
        __syncthreads();
        if (tid == 0 && cta == 1) flag_set(&g_f2);   // only R1 needs a flag
    }

    if (cta == 0) {
        if (tid == 0) flag_wait_reset(&g_f2);
        __syncthreads();
        __threadfence();
        compose_mma(g_R[0].M, g_R[0].c, g_R[1].M, g_R[1].c, g_S.M, g_S.c);
        __syncthreads();                 // own-CTA visibility for S
        if (tid == 0) flag_wait_reset(&g_f1[4]);
        __syncthreads();
        __threadfence();
        compose_mma(g_S.M, g_S.c, g_Q[4].M, g_Q[4].c, g_final.M, g_final.c);
    }
}

// ---------------------------------------------------------------------------
// Apply: out = x @ Mc^T + c via mma.sync m16n8k16 bf16x3.
// CTA = 256 threads = 8 warps; warp (w>>1, w&1) -> 16x32 block.
// 256 rows per CTA (4 blocks of 64); B fragments + bias loaded ONCE per CTA.
// ---------------------------------------------------------------------------
__global__ void __launch_bounds__(256)
apply_kernel(const float* __restrict__ x, float* __restrict__ out) {
    const int tid  = threadIdx.x;
    const int lane = tid & 31;
    const int w    = tid >> 5;
    const int g    = lane >> 2;
    const int tig  = lane & 3;
    const int warp_r = (w >> 1) * 16;
    const int warp_c = (w & 1) * 32;

    const float* __restrict__ Mc = g_final.M;
    const float* __restrict__ cc = g_final.c;

    // B fragments (composite, row n contiguous in k), bf16x3 split
    uint32_t bhi[4][4][2], blo[4][4][2];
#pragma unroll
    for (int kt = 0; kt < 4; kt++)
#pragma unroll
        for (int nt = 0; nt < 4; nt++) {
            int n = warp_c + nt * 8 + g;
            const float* br = Mc + n * DIM + kt * 16 + 2 * tig;
            float2 p0 = *reinterpret_cast<const float2*>(br);
            float2 p1 = *reinterpret_cast<const float2*>(br + 8);
            split2(p0, bhi[kt][nt][0], blo[kt][nt][0]);
            split2(p1, bhi[kt][nt][1], blo[kt][nt][1]);
        }

    float2 bias[4];
#pragma unroll
    for (int nt = 0; nt < 4; nt++) {
        int col = warp_c + nt * 8 + 2 * tig;
        bias[nt] = *reinterpret_cast<const float2*>(cc + col);
    }

    const size_t base = (size_t)blockIdx.x * ROWS_PER_CTA;
#pragma unroll 1
    for (int blk = 0; blk < ROWS_PER_CTA / 64; blk++) {
        const size_t r0 = base + blk * 64 + warp_r + g;
        const float* __restrict__ xr = x + r0 * DIM;

        float acc[4][4] = {};
#pragma unroll
        for (int kt = 0; kt < 4; kt++) {
            int kk = kt * 16 + 2 * tig;
            float2 a00 = *reinterpret_cast<const float2*>(xr + kk);
            float2 a10 = *reinterpret_cast<const float2*>(xr + 8 * DIM + kk);
            float2 a01 = *reinterpret_cast<const float2*>(xr + kk + 8);
            float2 a11 = *reinterpret_cast<const float2*>(xr + 8 * DIM + kk + 8);
            uint32_t ahi[4], alo[4];
            split2(a00, ahi[0], alo[0]);
            split2(a10, ahi[1], alo[1]);
            split2(a01, ahi[2], alo[2]);
            split2(a11, ahi[3], alo[3]);
#pragma unroll
            for (int nt = 0; nt < 4; nt++) {
                mma16816(acc[nt], ahi, bhi[kt][nt]);
                mma16816(acc[nt], ahi, blo[kt][nt]);
                mma16816(acc[nt], alo, bhi[kt][nt]);
            }
        }

        float* __restrict__ orow = out + r0 * DIM;
#pragma unroll
        for (int nt = 0; nt < 4; nt++) {
            int col = warp_c + nt * 8 + 2 * tig;
            *reinterpret_cast<float2*>(orow + col) =
                make_float2(acc[nt][0] + bias[nt].x, acc[nt][1] + bias[nt].y);
            *reinterpret_cast<float2*>(orow + 8 * DIM + col) =
                make_float2(acc[nt][2] + bias[nt].x, acc[nt][3] + bias[nt].y);
        }
    }
}

// ---------------------------------------------------------------------------
// Launch
// ---------------------------------------------------------------------------
extern "C" void kernel_launch(void* const* d_in, const int* in_sizes, int n_in,
                              void* d_out, int out_size) {
    const float* x = (const float*)d_in[0];  // [524288, 64]
    const float* W = (const float*)d_in[1];  // [20, 64, 64]
    const float* b = (const float*)d_in[2];  // [20, 64]
    float* out = (float*)d_out;              // [524288, 64]

    compose_kernel<<<10, 256>>>(W, b);
    apply_kernel<<<N_TOK / ROWS_PER_CTA, 256>>>(x, out);
}

// round 7
// speedup vs baseline: 1.0224x; 1.0224x over previous
#include <cuda_runtime.h>
#include <cuda_bf16.h>
#include <cstdint>

// ============================================================================
// out = chain of 20 Linear(64,64) over x[524288,64], fp32.
// Affine chain => compose into ONE map (Mc, c): out = x @ Mc^T + c.
//   Kernel 1: compose_kernel — ONE CTA, 19 sequential smem-resident composes
//             via mma.sync bf16x4 (no cross-CTA sync).
//   Kernel 2: apply_kernel — mma.sync m16n8k16 bf16x3, B frags in regs,
//             __launch_bounds__(256,2) for 2 CTAs/SM, bias folded into acc.
// Base sm_103 target (no tcgen05 in this build pipeline).
// ============================================================================

#define N_TOK   524288
#define DIM     64
#define LAYERS  20
#define ROWS_PER_CTA 256
#define PITCH   68   // smem row pitch (floats): bank = (4t+n)%32, conflict-free

struct AffineMap {
    float M[DIM * DIM];
    float c[DIM];
};
__device__ AffineMap g_final;

// ---------------------------------------------------------------------------
// bf16 split + mma.sync helpers
// ---------------------------------------------------------------------------
__device__ __forceinline__ void split2(float2 v, uint32_t& hi, uint32_t& lo) {
    __nv_bfloat16 hx = __float2bfloat16_rn(v.x);
    __nv_bfloat16 hy = __float2bfloat16_rn(v.y);
    __nv_bfloat16 lx = __float2bfloat16_rn(v.x - __bfloat162float(hx));
    __nv_bfloat16 ly = __float2bfloat16_rn(v.y - __bfloat162float(hy));
    hi = (uint32_t)__bfloat16_as_ushort(hx) |
         ((uint32_t)__bfloat16_as_ushort(hy) << 16);
    lo = (uint32_t)__bfloat16_as_ushort(lx) |
         ((uint32_t)__bfloat16_as_ushort(ly) << 16);
}

__device__ __forceinline__ void mma16816(float* c, const uint32_t* a,
                                         const uint32_t* b) {
    asm volatile(
        "mma.sync.aligned.m16n8k16.row.col.f32.bf16.bf16.f32 "
        "{%0,%1,%2,%3}, {%4,%5,%6,%7}, {%8,%9}, {%0,%1,%2,%3};\n"
        : "+f"(c[0]), "+f"(c[1]), "+f"(c[2]), "+f"(c[3])
        : "r"(a[0]), "r"(a[1]), "r"(a[2]), "r"(a[3]), "r"(b[0]), "r"(b[1]));
}

// ---------------------------------------------------------------------------
// Compose kernel: single CTA (256 threads), 19 sequential steps.
// cur lives in double-buffered smem [64][PITCH]; step: new = W_l @ cur,
// c_new = W_l @ c + b_l. mma bf16x4 (all four split terms).
// ---------------------------------------------------------------------------
__global__ void __launch_bounds__(256)
compose_kernel(const float* __restrict__ W, const float* __restrict__ bb) {
    __shared__ float sM[2][DIM][PITCH];
    __shared__ float sc[2][DIM];

    const int tid  = threadIdx.x;
    const int lane = tid & 31;
    const int w    = tid >> 5;
    const int g    = lane >> 2;
    const int tig  = lane & 3;
    const int warp_r = (w >> 1) * 16;
    const int warp_c = (w & 1) * 32;

    // Init cur = layer 0
    {
        const float4* W0 = reinterpret_cast<const float4*>(W);
#pragma unroll
        for (int it = 0; it < 4; it++) {
            int f = tid + it * 256;          // float4 index 0..1023
            float4 v = W0[f];
            int row = f >> 4;
            int c4  = (f & 15) * 4;
            *reinterpret_cast<float4*>(&sM[0][row][c4]) = v;
        }
        if (tid < DIM) sc[0][tid] = bb[tid];
    }
    __syncthreads();

    for (int l = 1; l < LAYERS; l++) {
        const int s = (l - 1) & 1;
        const int d = l & 1;
        const float* __restrict__ Wl = W + (size_t)l * DIM * DIM;

        // B fragments from smem cur: B[n][t] = cur[t][n]  (column gather,
        // conflict-free with PITCH=68). 4-term split.
        uint32_t bhi[4][4][2], blo[4][4][2];
#pragma unroll
        for (int kt = 0; kt < 4; kt++)
#pragma unroll
            for (int nt = 0; nt < 4; nt++) {
                int n  = warp_c + nt * 8 + g;
                int t0 = kt * 16 + 2 * tig;
                float2 p0 = make_float2(sM[s][t0 + 0][n], sM[s][t0 + 1][n]);
                float2 p1 = make_float2(sM[s][t0 + 8][n], sM[s][t0 + 9][n]);
                split2(p0, bhi[kt][nt][0], blo[kt][nt][0]);
                split2(p1, bhi[kt][nt][1], blo[kt][nt][1]);
            }

        // A fragments from W_l rows (gmem, L1-hot) + MMA (hh, hl, lh, ll)
        const float* ar = Wl + (size_t)(warp_r + g) * DIM;
        float acc[4][4] = {};
#pragma unroll
        for (int kt = 0; kt < 4; kt++) {
            int t0 = kt * 16 + 2 * tig;
            float2 a00 = *reinterpret_cast<const float2*>(ar + t0);
            float2 a10 = *reinterpret_cast<const float2*>(ar + 8 * DIM + t0);
            float2 a01 = *reinterpret_cast<const float2*>(ar + t0 + 8);
            float2 a11 = *reinterpret_cast<const float2*>(ar + 8 * DIM + t0 + 8);
            uint32_t ahi[4], alo[4];
            split2(a00, ahi[0], alo[0]);
            split2(a10, ahi[1], alo[1]);
            split2(a01, ahi[2], alo[2]);
            split2(a11, ahi[3], alo[3]);
#pragma unroll
            for (int nt = 0; nt < 4; nt++) {
                mma16816(acc[nt], ahi, bhi[kt][nt]);
                mma16816(acc[nt], ahi, blo[kt][nt]);
                mma16816(acc[nt], alo, bhi[kt][nt]);
                mma16816(acc[nt], alo, blo[kt][nt]);
            }
        }

        // Store new M to the other buffer
#pragma unroll
        for (int nt = 0; nt < 4; nt++) {
            int col = warp_c + nt * 8 + 2 * tig;
            int row = warp_r + g;
            *reinterpret_cast<float2*>(&sM[d][row][col]) =
                make_float2(acc[nt][0], acc[nt][1]);
            *reinterpret_cast<float2*>(&sM[d][row + 8][col]) =
                make_float2(acc[nt][2], acc[nt][3]);
        }

        // Bias: c_new[j] = b_l[j] + sum_t W_l[j][t] * c[t]   (fp32)
        if (tid < DIM) {
            int j = tid;
            const float4* wr = reinterpret_cast<const float4*>(Wl + j * DIM);
            float sacc = bb[l * DIM + j];
#pragma unroll
            for (int t4 = 0; t4 < 16; t4++) {
                float4 wv = wr[t4];
                sacc += wv.x * sc[s][4 * t4 + 0] + wv.y * sc[s][4 * t4 + 1] +
                        wv.z * sc[s][4 * t4 + 2] + wv.w * sc[s][4 * t4 + 3];
            }
            sc[d][j] = sacc;
        }
        __syncthreads();
    }

    // Write final map to gmem (cur is in buffer (LAYERS-1)&1 = 1)
    {
        const int fb = (LAYERS - 1) & 1;
#pragma unroll
        for (int it = 0; it < 4; it++) {
            int f = tid + it * 256;
            int row = f >> 4;
            int c4  = (f & 15) * 4;
            *reinterpret_cast<float4*>(&g_final.M[row * DIM + c4]) =
                *reinterpret_cast<const float4*>(&sM[fb][row][c4]);
        }
        if (tid < DIM) g_final.c[tid] = sc[fb][tid];
    }
}

// ---------------------------------------------------------------------------
// Apply: out = x @ Mc^T + c via mma.sync m16n8k16 bf16x3.
// CTA = 256 threads = 8 warps; warp (w>>1, w&1) -> 16x32 block; 256 rows/CTA.
// B fragments + bias loaded ONCE per CTA; bias folded into acc init.
// __launch_bounds__(256, 2): cap regs at 128 so 2 CTAs fit per SM.
// ---------------------------------------------------------------------------
__global__ void __launch_bounds__(256, 2)
apply_kernel(const float* __restrict__ x, float* __restrict__ out) {
    const int tid  = threadIdx.x;
    const int lane = tid & 31;
    const int w    = tid >> 5;
    const int g    = lane >> 2;
    const int tig  = lane & 3;
    const int warp_r = (w >> 1) * 16;
    const int warp_c = (w & 1) * 32;

    const float* __restrict__ Mc = g_final.M;
    const float* __restrict__ cc = g_final.c;

    // B fragments (row n contiguous in k), bf16x3 split, resident in regs
    uint32_t bhi[4][4][2], blo[4][4][2];
#pragma unroll
    for (int kt = 0; kt < 4; kt++)
#pragma unroll
        for (int nt = 0; nt < 4; nt++) {
            int n = warp_c + nt * 8 + g;
            const float* br = Mc + n * DIM + kt * 16 + 2 * tig;
            float2 p0 = *reinterpret_cast<const float2*>(br);
            float2 p1 = *reinterpret_cast<const float2*>(br + 8);
            split2(p0, bhi[kt][nt][0], blo[kt][nt][0]);
            split2(p1, bhi[kt][nt][1], blo[kt][nt][1]);
        }

    float2 bias[4];
#pragma unroll
    for (int nt = 0; nt < 4; nt++) {
        int col = warp_c + nt * 8 + 2 * tig;
        bias[nt] = *reinterpret_cast<const float2*>(cc + col);
    }

    const size_t base = (size_t)blockIdx.x * ROWS_PER_CTA;
#pragma unroll 1
    for (int blk = 0; blk < ROWS_PER_CTA / 64; blk++) {
        const size_t r0 = base + blk * 64 + warp_r + g;
        const float* __restrict__ xr = x + r0 * DIM;

        // acc initialized with bias (epilogue add eliminated)
        float acc[4][4];
#pragma unroll
        for (int nt = 0; nt < 4; nt++) {
            acc[nt][0] = bias[nt].x; acc[nt][1] = bias[nt].y;
            acc[nt][2] = bias[nt].x; acc[nt][3] = bias[nt].y;
        }

#pragma unroll
        for (int kt = 0; kt < 4; kt++) {
            int kk = kt * 16 + 2 * tig;
            float2 a00 = *reinterpret_cast<const float2*>(xr + kk);
            float2 a10 = *reinterpret_cast<const float2*>(xr + 8 * DIM + kk);
            float2 a01 = *reinterpret_cast<const float2*>(xr + kk + 8);
            float2 a11 = *reinterpret_cast<const float2*>(xr + 8 * DIM + kk + 8);
            uint32_t ahi[4], alo[4];
            split2(a00, ahi[0], alo[0]);
            split2(a10, ahi[1], alo[1]);
            split2(a01, ahi[2], alo[2]);
            split2(a11, ahi[3], alo[3]);
#pragma unroll
            for (int nt = 0; nt < 4; nt++) {
                mma16816(acc[nt], ahi, bhi[kt][nt]);
                mma16816(acc[nt], ahi, blo[kt][nt]);
                mma16816(acc[nt], alo, bhi[kt][nt]);
            }
        }

        float* __restrict__ orow = out + r0 * DIM;
#pragma unroll
        for (int nt = 0; nt < 4; nt++) {
            int col = warp_c + nt * 8 + 2 * tig;
            *reinterpret_cast<float2*>(orow + col) =
                make_float2(acc[nt][0], acc[nt][1]);
            *reinterpret_cast<float2*>(orow + 8 * DIM + col) =
                make_float2(acc[nt][2], acc[nt][3]);
        }
    }
}

// ---------------------------------------------------------------------------
// Launch
// ---------------------------------------------------------------------------
extern "C" void kernel_launch(void* const* d_in, const int* in_sizes, int n_in,
                              void* d_out, int out_size) {
    const float* x = (const float*)d_in[0];  // [524288, 64]
    const float* W = (const float*)d_in[1];  // [20, 64, 64]
    const float* b = (const float*)d_in[2];  // [20, 64]
    float* out = (float*)d_out;              // [524288, 64]

    compose_kernel<<<1, 256>>>(W, b);
    apply_kernel<<<N_TOK / ROWS_PER_CTA, 256>>>(x, out);
}

// round 8
// speedup vs baseline: 1.2762x; 1.2482x over previous
#include <cuda_runtime.h>
#include <cuda_bf16.h>
#include <cstdint>

// ============================================================================
// out = chain of 20 Linear(64,64) over x[524288,64], fp32.
// Affine chain => compose into ONE map (Mc, c): out = x @ Mc^T + c.
//   Kernel 1: compose_kernel — ONE CTA, 19 sequential smem-resident composes
//             via mma.sync bf16x4, with register prefetch of next layer's
//             A fragments to hide DRAM latency.
//   Kernel 2: apply_kernel — persistent CTAs, cp.async double-buffered x
//             tiles in smem, mma.sync bf16x3, smem-staged coalesced epilogue.
// Base sm_103 target (no tcgen05 in this build pipeline).
// ============================================================================

#define N_TOK   524288
#define DIM     64
#define LAYERS  20
#define PIT     68            // smem pitch (floats): conflict-free frag LDS
#define TILE_R  128
#define NT      (N_TOK / TILE_R)   // 4096 tiles
#define GRID_APPLY 304             // 2 x 152 SMs (GB300)

struct AffineMap {
    float M[DIM * DIM];
    float c[DIM];
};
__device__ AffineMap g_final;

// ---------------------------------------------------------------------------
// helpers
// ---------------------------------------------------------------------------
__device__ __forceinline__ void split2(float2 v, uint32_t& hi, uint32_t& lo) {
    __nv_bfloat16 hx = __float2bfloat16_rn(v.x);
    __nv_bfloat16 hy = __float2bfloat16_rn(v.y);
    __nv_bfloat16 lx = __float2bfloat16_rn(v.x - __bfloat162float(hx));
    __nv_bfloat16 ly = __float2bfloat16_rn(v.y - __bfloat162float(hy));
    hi = (uint32_t)__bfloat16_as_ushort(hx) |
         ((uint32_t)__bfloat16_as_ushort(hy) << 16);
    lo = (uint32_t)__bfloat16_as_ushort(lx) |
         ((uint32_t)__bfloat16_as_ushort(ly) << 16);
}

__device__ __forceinline__ void mma16816(float* c, const uint32_t* a,
                                         const uint32_t* b) {
    asm volatile(
        "mma.sync.aligned.m16n8k16.row.col.f32.bf16.bf16.f32 "
        "{%0,%1,%2,%3}, {%4,%5,%6,%7}, {%8,%9}, {%0,%1,%2,%3};\n"
        : "+f"(c[0]), "+f"(c[1]), "+f"(c[2]), "+f"(c[3])
        : "r"(a[0]), "r"(a[1]), "r"(a[2]), "r"(a[3]), "r"(b[0]), "r"(b[1]));
}

__device__ __forceinline__ uint32_t smem_u32(const void* p) {
    uint32_t a;
    asm("{ .reg .u64 t; cvta.to.shared.u64 t, %1; cvt.u32.u64 %0, t; }"
        : "=r"(a) : "l"(p));
    return a;
}

#define CP_ASYNC16(saddr, gptr) \
    asm volatile("cp.async.cg.shared.global [%0], [%1], 16;" \
                 :: "r"(saddr), "l"(gptr))
#define CP_COMMIT() asm volatile("cp.async.commit_group;")
#define CP_WAIT(n)  asm volatile("cp.async.wait_group %0;" :: "n"(n))

// ---------------------------------------------------------------------------
// Compose kernel: single CTA, 19 sequential steps, A-frag register prefetch.
// cur in double-buffered smem [64][PIT]; step: new = W_l @ cur (mma bf16x4),
// c_new = W_l @ c + b_l (4 independent partial chains).
// ---------------------------------------------------------------------------
__global__ void __launch_bounds__(256)
compose_kernel(const float* __restrict__ W, const float* __restrict__ bb) {
    __shared__ float sM[2][DIM][PIT];
    __shared__ float sc[2][DIM];

    const int tid  = threadIdx.x;
    const int lane = tid & 31;
    const int w    = tid >> 5;
    const int g    = lane >> 2;
    const int tig  = lane & 3;
    const int warp_r = (w >> 1) * 16;
    const int warp_c = (w & 1) * 32;

    // cur = layer 0
    {
        const float4* W0 = reinterpret_cast<const float4*>(W);
#pragma unroll
        for (int it = 0; it < 4; it++) {
            int f = tid + it * 256;          // float4 index 0..1023
            float4 v = W0[f];
            int row = f >> 4;
            int c4  = (f & 15) * 4;
            *reinterpret_cast<float4*>(&sM[0][row][c4]) = v;
        }
        if (tid < DIM) sc[0][tid] = bb[tid];
    }

    // Prefetch layer-1 A fragments into registers (before the barrier: they
    // don't depend on smem).
    float2 aN[16];
    {
        const float* ar = W + (size_t)1 * DIM * DIM + (size_t)(warp_r + g) * DIM;
#pragma unroll
        for (int kt = 0; kt < 4; kt++) {
            int t0 = kt * 16 + 2 * tig;
            aN[kt * 4 + 0] = *reinterpret_cast<const float2*>(ar + t0);
            aN[kt * 4 + 1] = *reinterpret_cast<const float2*>(ar + 8 * DIM + t0);
            aN[kt * 4 + 2] = *reinterpret_cast<const float2*>(ar + t0 + 8);
            aN[kt * 4 + 3] = *reinterpret_cast<const float2*>(ar + 8 * DIM + t0 + 8);
        }
    }
    __syncthreads();

    for (int l = 1; l < LAYERS; l++) {
        const int s = (l - 1) & 1;
        const int d = l & 1;

        // current A frags; immediately issue next layer's loads (overlap DRAM)
        float2 aC[16];
#pragma unroll
        for (int i = 0; i < 16; i++) aC[i] = aN[i];
        if (l + 1 < LAYERS) {
            const float* ar = W + (size_t)(l + 1) * DIM * DIM +
                              (size_t)(warp_r + g) * DIM;
#pragma unroll
            for (int kt = 0; kt < 4; kt++) {
                int t0 = kt * 16 + 2 * tig;
                aN[kt * 4 + 0] = *reinterpret_cast<const float2*>(ar + t0);
                aN[kt * 4 + 1] = *reinterpret_cast<const float2*>(ar + 8 * DIM + t0);
                aN[kt * 4 + 2] = *reinterpret_cast<const float2*>(ar + t0 + 8);
                aN[kt * 4 + 3] = *reinterpret_cast<const float2*>(ar + 8 * DIM + t0 + 8);
            }
        }

        // B fragments from smem cur: B[n][t] = cur[t][n] (conflict-free, PIT=68)
        uint32_t bhi[4][4][2], blo[4][4][2];
#pragma unroll
        for (int kt = 0; kt < 4; kt++)
#pragma unroll
            for (int nt = 0; nt < 4; nt++) {
                int n  = warp_c + nt * 8 + g;
                int t0 = kt * 16 + 2 * tig;
                float2 p0 = make_float2(sM[s][t0 + 0][n], sM[s][t0 + 1][n]);
                float2 p1 = make_float2(sM[s][t0 + 8][n], sM[s][t0 + 9][n]);
                split2(p0, bhi[kt][nt][0], blo[kt][nt][0]);
                split2(p1, bhi[kt][nt][1], blo[kt][nt][1]);
            }

        // MMA: 4-term bf16 split (hh, hl, lh, ll)
        float acc[4][4] = {};
#pragma unroll
        for (int kt = 0; kt < 4; kt++) {
            uint32_t ahi[4], alo[4];
            split2(aC[kt * 4 + 0], ahi[0], alo[0]);
            split2(aC[kt * 4 + 1], ahi[1], alo[1]);
            split2(aC[kt * 4 + 2], ahi[2], alo[2]);
            split2(aC[kt * 4 + 3], ahi[3], alo[3]);
#pragma unroll
            for (int nt = 0; nt < 4; nt++) {
                mma16816(acc[nt], ahi, bhi[kt][nt]);
                mma16816(acc[nt], ahi, blo[kt][nt]);
                mma16816(acc[nt], alo, bhi[kt][nt]);
                mma16816(acc[nt], alo, blo[kt][nt]);
            }
        }

        // store new M
#pragma unroll
        for (int nt = 0; nt < 4; nt++) {
            int col = warp_c + nt * 8 + 2 * tig;
            int row = warp_r + g;
            *reinterpret_cast<float2*>(&sM[d][row][col]) =
                make_float2(acc[nt][0], acc[nt][1]);
            *reinterpret_cast<float2*>(&sM[d][row + 8][col]) =
                make_float2(acc[nt][2], acc[nt][3]);
        }

        // bias: c_new[j] = b_l[j] + sum_t W_l[j][t]*c[t], 4 partial chains
        if (tid < DIM) {
            int j = tid;
            const float4* wr = reinterpret_cast<const float4*>(
                W + (size_t)l * DIM * DIM + (size_t)j * DIM);
            float p0 = 0.f, p1 = 0.f, p2 = 0.f, p3 = 0.f;
#pragma unroll
            for (int t4 = 0; t4 < 16; t4 += 4) {
                float4 w0 = wr[t4 + 0], w1 = wr[t4 + 1];
                float4 w2 = wr[t4 + 2], w3 = wr[t4 + 3];
                p0 += w0.x * sc[s][4 * t4 + 0] + w0.y * sc[s][4 * t4 + 1] +
                      w0.z * sc[s][4 * t4 + 2] + w0.w * sc[s][4 * t4 + 3];
                p1 += w1.x * sc[s][4 * t4 + 4] + w1.y * sc[s][4 * t4 + 5] +
                      w1.z * sc[s][4 * t4 + 6] + w1.w * sc[s][4 * t4 + 7];
                p2 += w2.x * sc[s][4 * t4 + 8] + w2.y * sc[s][4 * t4 + 9] +
                      w2.z * sc[s][4 * t4 + 10] + w2.w * sc[s][4 * t4 + 11];
                p3 += w3.x * sc[s][4 * t4 + 12] + w3.y * sc[s][4 * t4 + 13] +
                      w3.z * sc[s][4 * t4 + 14] + w3.w * sc[s][4 * t4 + 15];
            }
            sc[d][j] = bb[l * DIM + j] + ((p0 + p1) + (p2 + p3));
        }
        __syncthreads();
    }

    // final map is in buffer (LAYERS-1)&1 = 1
    {
#pragma unroll
        for (int it = 0; it < 4; it++) {
            int f = tid + it * 256;
            int row = f >> 4;
            int c4  = (f & 15) * 4;
            *reinterpret_cast<float4*>(&g_final.M[row * DIM + c4]) =
                *reinterpret_cast<const float4*>(&sM[1][row][c4]);
        }
        if (tid < DIM) g_final.c[tid] = sc[1][tid];
    }
}

// ---------------------------------------------------------------------------
// Apply: out = x @ Mc^T + c. Persistent CTAs, cp.async double-buffered
// 128x64 x-tiles, mma.sync bf16x3, smem-staged coalesced epilogue.
// smem: 2*[128][PIT] x-buffers + [64][PIT] out-stage = 87040 B (dynamic).
// ---------------------------------------------------------------------------
__global__ void __launch_bounds__(256, 2)
apply_kernel(const float* __restrict__ x, float* __restrict__ out) {
    extern __shared__ float sm[];
    float* xs0 = sm;                       // [128][PIT]
    float* xs1 = sm + TILE_R * PIT;        // [128][PIT]
    float* os  = sm + 2 * TILE_R * PIT;    // [64][PIT]

    const int tid  = threadIdx.x;
    const int lane = tid & 31;
    const int w    = tid >> 5;
    const int g    = lane >> 2;
    const int tig  = lane & 3;
    const int warp_r = (w >> 1) * 16;
    const int warp_c = (w & 1) * 32;

    const uint32_t xsa0 = smem_u32(xs0);
    const uint32_t xsa1 = smem_u32(xs1);

    // kick off first tile's prefetch before anything else
    int t = blockIdx.x;
    if (t < NT) {
        const float* src = x + (size_t)t * TILE_R * DIM;
#pragma unroll
        for (int i = 0; i < 8; i++) {
            int id  = tid + i * 256;            // 16B-chunk id, 0..2047
            int row = id >> 4, ch = id & 15;
            CP_ASYNC16(xsa0 + (uint32_t)(row * PIT + ch * 4) * 4, src + id * 4);
        }
        CP_COMMIT();
    }

    // B fragments (composite map, L2-hot) + bias — loaded while tile0 flies
    const float* __restrict__ Mc = g_final.M;
    const float* __restrict__ cc = g_final.c;
    uint32_t bhi[4][4][2], blo[4][4][2];
#pragma unroll
    for (int kt = 0; kt < 4; kt++)
#pragma unroll
        for (int nt = 0; nt < 4; nt++) {
            int n = warp_c + nt * 8 + g;
            const float* br = Mc + n * DIM + kt * 16 + 2 * tig;
            float2 p0 = *reinterpret_cast<const float2*>(br);
            float2 p1 = *reinterpret_cast<const float2*>(br + 8);
            split2(p0, bhi[kt][nt][0], blo[kt][nt][0]);
            split2(p1, bhi[kt][nt][1], blo[kt][nt][1]);
        }
    float2 bias[4];
#pragma unroll
    for (int nt = 0; nt < 4; nt++) {
        int col = warp_c + nt * 8 + 2 * tig;
        bias[nt] = *reinterpret_cast<const float2*>(cc + col);
    }

    int buf = 0;
    while (t < NT) {
        const int tn = t + GRID_APPLY;
        if (tn < NT) {   // prefetch next tile into the other buffer
            const uint32_t sb = buf ? xsa0 : xsa1;
            const float* src = x + (size_t)tn * TILE_R * DIM;
#pragma unroll
            for (int i = 0; i < 8; i++) {
                int id  = tid + i * 256;
                int row = id >> 4, ch = id & 15;
                CP_ASYNC16(sb + (uint32_t)(row * PIT + ch * 4) * 4, src + id * 4);
            }
            CP_COMMIT();
            CP_WAIT(1);   // tile t has landed
        } else {
            CP_WAIT(0);
        }
        __syncthreads();

        const float* xb = buf ? xs1 : xs0;
#pragma unroll
        for (int blk = 0; blk < 2; blk++) {
            const float* xr = xb + (size_t)(blk * 64 + warp_r + g) * PIT;

            float acc[4][4];
#pragma unroll
            for (int nt = 0; nt < 4; nt++) {
                acc[nt][0] = bias[nt].x; acc[nt][1] = bias[nt].y;
                acc[nt][2] = bias[nt].x; acc[nt][3] = bias[nt].y;
            }

#pragma unroll
            for (int kt = 0; kt < 4; kt++) {
                int kk = kt * 16 + 2 * tig;
                float2 a00 = *reinterpret_cast<const float2*>(xr + kk);
                float2 a10 = *reinterpret_cast<const float2*>(xr + 8 * PIT + kk);
                float2 a01 = *reinterpret_cast<const float2*>(xr + kk + 8);
                float2 a11 = *reinterpret_cast<const float2*>(xr + 8 * PIT + kk + 8);
                uint32_t ahi[4], alo[4];
                split2(a00, ahi[0], alo[0]);
                split2(a10, ahi[1], alo[1]);
                split2(a01, ahi[2], alo[2]);
                split2(a11, ahi[3], alo[3]);
#pragma unroll
                for (int nt = 0; nt < 4; nt++) {
                    mma16816(acc[nt], ahi, bhi[kt][nt]);
                    mma16816(acc[nt], ahi, blo[kt][nt]);
                    mma16816(acc[nt], alo, bhi[kt][nt]);
                }
            }

            // stage through smem for coalesced 128-bit stores
            __syncthreads();   // prior os readers done
            float* o0 = os + (size_t)(warp_r + g) * PIT;
#pragma unroll
            for (int nt = 0; nt < 4; nt++) {
                int col = warp_c + nt * 8 + 2 * tig;
                *reinterpret_cast<float2*>(o0 + col) =
                    make_float2(acc[nt][0], acc[nt][1]);
                *reinterpret_cast<float2*>(o0 + 8 * PIT + col) =
                    make_float2(acc[nt][2], acc[nt][3]);
            }
            __syncthreads();

            float* gdst = out + ((size_t)t * TILE_R + blk * 64) * DIM;
#pragma unroll
            for (int i = 0; i < 4; i++) {
                int id  = tid + i * 256;        // float4 id, 0..1023
                int row = id >> 4, ch = id & 15;
                float4 v = *reinterpret_cast<const float4*>(os + row * PIT + ch * 4);
                *reinterpret_cast<float4*>(gdst + id * 4) = v;
            }
        }
        buf ^= 1;
        t = tn;
    }
}

// ---------------------------------------------------------------------------
// Launch
// ---------------------------------------------------------------------------
extern "C" void kernel_launch(void* const* d_in, const int* in_sizes, int n_in,
                              void* d_out, int out_size) {
    const float* x = (const float*)d_in[0];  // [524288, 64]
    const float* W = (const float*)d_in[1];  // [20, 64, 64]
    const float* b = (const float*)d_in[2];  // [20, 64]
    float* out = (float*)d_out;              // [524288, 64]

    static int smem_set = 0;
    const int smem_bytes = (2 * TILE_R * PIT + 64 * PIT) * (int)sizeof(float);
    if (!smem_set) {
        cudaFuncSetAttribute(apply_kernel,
                             cudaFuncAttributeMaxDynamicSharedMemorySize,
                             smem_bytes);
        smem_set = 1;
    }

    compose_kernel<<<1, 256>>>(W, b);
    apply_kernel<<<GRID_APPLY, 256, smem_bytes>>>(x, out);
}

// round 14
// speedup vs baseline: 1.9006x; 1.4892x over previous
#include <cuda_runtime.h>
#include <cuda_bf16.h>
#include <cstdint>

// ============================================================================
// out = chain of 20 Linear(64,64) over x[524288,64], fp32.
// Affine chain => compose into ONE map (Mc, c): out = x @ Mc^T + c.
//   Compose: 5-launch tree (10 -> 5 -> 2 -> 1 -> 1 CTAs), NO cross-CTA
//            spin-flags (launch boundaries give ordering). Each 64x64x64
//            product: cp.async-staged operands in smem + mma.sync bf16x3,
//            bias path exact fp32.
//   Apply:   persistent, 3 CTAs/SM, cp.async double-buffered 64-row tiles,
//            B fragments in a packed smem table (one LDS.128 per (kt,nt)),
//            smem-staged coalesced epilogue.
// Base sm_103 target (no tcgen05 in this build pipeline).
// ============================================================================

#define N_TOK   524288
#define DIM     64
#define TILE_R  64
#define NT      (N_TOK / TILE_R)     // 8192 tiles
#define GRID_APPLY 456               // 3 x 152 SMs
#define PIT     72                   // apply smem pitch (floats), 16B-aligned
#define PITC    68                   // compose smem pitch, 16B-aligned

struct AffineMap {
    float M[DIM * DIM];
    float c[DIM];
};
__device__ AffineMap g_final;
__device__ AffineMap g_P[10];   // level 0 results
__device__ AffineMap g_Q[5];    // level 1 results
__device__ AffineMap g_R[2];    // level 2 results
__device__ AffineMap g_S;       // level 3 result (layers 0..15)

// ---------------------------------------------------------------------------
// helpers
// ---------------------------------------------------------------------------
__device__ __forceinline__ void split2(float2 v, uint32_t& hi, uint32_t& lo) {
    __nv_bfloat16 hx = __float2bfloat16_rn(v.x);
    __nv_bfloat16 hy = __float2bfloat16_rn(v.y);
    __nv_bfloat16 lx = __float2bfloat16_rn(v.x - __bfloat162float(hx));
    __nv_bfloat16 ly = __float2bfloat16_rn(v.y - __bfloat162float(hy));
    hi = (uint32_t)__bfloat16_as_ushort(hx) |
         ((uint32_t)__bfloat16_as_ushort(hy) << 16);
    lo = (uint32_t)__bfloat16_as_ushort(lx) |
         ((uint32_t)__bfloat16_as_ushort(ly) << 16);
}

__device__ __forceinline__ void mma16816(float* c, const uint32_t* a,
                                         uint32_t b0, uint32_t b1) {
    asm volatile(
        "mma.sync.aligned.m16n8k16.row.col.f32.bf16.bf16.f32 "
        "{%0,%1,%2,%3}, {%4,%5,%6,%7}, {%8,%9}, {%0,%1,%2,%3};\n"
        : "+f"(c[0]), "+f"(c[1]), "+f"(c[2]), "+f"(c[3])
        : "r"(a[0]), "r"(a[1]), "r"(a[2]), "r"(a[3]), "r"(b0), "r"(b1));
}

__device__ __forceinline__ uint32_t smem_u32(const void* p) {
    uint32_t a;
    asm("{ .reg .u64 t; cvta.to.shared.u64 t, %1; cvt.u32.u64 %0, t; }"
        : "=r"(a) : "l"(p));
    return a;
}

#define CP_ASYNC16(saddr, gptr) \
    asm volatile("cp.async.cg.shared.global [%0], [%1], 16;" \
                 :: "r"(saddr), "l"(gptr))
#define CP_COMMIT() asm volatile("cp.async.commit_group;")
#define CP_WAIT(n)  asm volatile("cp.async.wait_group %0;" :: "n"(n))

// ---------------------------------------------------------------------------
// One 64x64x64 affine compose on a 256-thread CTA.
// dst = Mb @ Ma (Ma applied first); dstc = Mb @ ca + cb (fp32).
// Operands cp.async-staged to smem (coalesced). Column gathers from sA are
// conflict-free with PITC=68.
// ---------------------------------------------------------------------------
__device__ void do_compose(const float* __restrict__ Ma,
                           const float* __restrict__ ca,
                           const float* __restrict__ Mb,
                           const float* __restrict__ cb,
                           float* __restrict__ dM,
                           float* __restrict__ dc,
                           float (*sA)[PITC], float (*sB)[PITC],
                           float* scv) {
    const int tid  = threadIdx.x;
    const int lane = tid & 31;
    const int w    = tid >> 5;
    const int g    = lane >> 2;
    const int tig  = lane & 3;
    const int warp_r = (w >> 1) * 16;
    const int warp_c = (w & 1) * 32;

    // stage Ma -> sA, Mb -> sB (1024 16B chunks each)
    {
        const uint32_t sa = smem_u32(&sA[0][0]);
        const uint32_t sb = smem_u32(&sB[0][0]);
#pragma unroll
        for (int i = 0; i < 4; i++) {
            int id = tid + i * 256;           // 0..1023
            int row = id >> 4, ch = id & 15;
            CP_ASYNC16(sa + (uint32_t)(row * PITC + ch * 4) * 4, Ma + id * 4);
            CP_ASYNC16(sb + (uint32_t)(row * PITC + ch * 4) * 4, Mb + id * 4);
        }
        CP_COMMIT();
    }
    if (tid < DIM) scv[tid] = ca[tid];
    CP_WAIT(0);
    __syncthreads();

    // B frags: B[n][t] = Ma[t][n] (column gather from sA), bf16x3 split
    uint32_t bhi[4][4][2], blo[4][4][2];
#pragma unroll
    for (int kt = 0; kt < 4; kt++)
#pragma unroll
        for (int nt = 0; nt < 4; nt++) {
            int n  = warp_c + nt * 8 + g;
            int t0 = kt * 16 + 2 * tig;
            float2 p0 = make_float2(sA[t0 + 0][n], sA[t0 + 1][n]);
            float2 p1 = make_float2(sA[t0 + 8][n], sA[t0 + 9][n]);
            split2(p0, bhi[kt][nt][0], blo[kt][nt][0]);
            split2(p1, bhi[kt][nt][1], blo[kt][nt][1]);
        }

    // A frags from sB rows + MMA (hh, hl, lh)
    float acc[4][4] = {};
#pragma unroll
    for (int kt = 0; kt < 4; kt++) {
        int t0 = kt * 16 + 2 * tig;
        const float* ar = &sB[warp_r + g][0];
        float2 a00 = make_float2(ar[t0], ar[t0 + 1]);
        float2 a01 = make_float2(ar[t0 + 8], ar[t0 + 9]);
        const float* ar8 = &sB[warp_r + g + 8][0];
        float2 a10 = make_float2(ar8[t0], ar8[t0 + 1]);
        float2 a11 = make_float2(ar8[t0 + 8], ar8[t0 + 9]);
        uint32_t ahi[4], alo[4];
        split2(a00, ahi[0], alo[0]);
        split2(a10, ahi[1], alo[1]);
        split2(a01, ahi[2], alo[2]);
        split2(a11, ahi[3], alo[3]);
#pragma unroll
        for (int nt = 0; nt < 4; nt++) {
            mma16816(acc[nt], ahi, bhi[kt][nt][0], bhi[kt][nt][1]);
            mma16816(acc[nt], ahi, blo[kt][nt][0], blo[kt][nt][1]);
            mma16816(acc[nt], alo, bhi[kt][nt][0], bhi[kt][nt][1]);
        }
    }

    // store dst matrix
#pragma unroll
    for (int nt = 0; nt < 4; nt++) {
        int col = warp_c + nt * 8 + 2 * tig;
        int row = warp_r + g;
        *reinterpret_cast<float2*>(dM + (size_t)row * DIM + col) =
            make_float2(acc[nt][0], acc[nt][1]);
        *reinterpret_cast<float2*>(dM + (size_t)(row + 8) * DIM + col) =
            make_float2(acc[nt][2], acc[nt][3]);
    }

    // bias (fp32 exact): dc[j] = cb[j] + sum_t Mb[j][t] * ca[t]
    if (tid < DIM) {
        int j = tid;
        float s = cb[j];
        float p0 = 0.f, p1 = 0.f;
#pragma unroll
        for (int t = 0; t < DIM; t += 4) {
            float2 w0 = *reinterpret_cast<const float2*>(&sB[j][t]);
            float2 w1 = *reinterpret_cast<const float2*>(&sB[j][t + 2]);
            p0 += w0.x * scv[t] + w0.y * scv[t + 1];
            p1 += w1.x * scv[t + 2] + w1.y * scv[t + 3];
        }
        dc[j] = s + (p0 + p1);
    }
}

// ---------------------------------------------------------------------------
// One tree level per launch (NO cross-CTA sync — ordering via launches).
// level 0 (10 CTAs): P[i]   = L(2i+1) o L(2i)      from raw W,b
// level 1 (5 CTAs):  Q[i]   = P[2i+1] o P[2i]
// level 2 (2 CTAs):  R[i]   = Q[2i+1] o Q[2i]
// level 3 (1 CTA):   S      = R[1] o R[0]          (layers 0..15)
// level 4 (1 CTA):   final  = Q[4] o S             (layers 0..19)
// ---------------------------------------------------------------------------
__global__ void __launch_bounds__(256)
compose_level_kernel(int level, const float* __restrict__ W,
                     const float* __restrict__ bb) {
    __shared__ float sA[DIM][PITC];
    __shared__ float sB[DIM][PITC];
    __shared__ float scv[DIM];

    const int cta = blockIdx.x;

    const float *Ma, *ca, *Mb, *cb;
    float *dM, *dc;
    switch (level) {
        case 0:
            Ma = W + (size_t)(2 * cta) * DIM * DIM;
            ca = bb + (2 * cta) * DIM;
            Mb = W + (size_t)(2 * cta + 1) * DIM * DIM;
            cb = bb + (2 * cta + 1) * DIM;
            dM = g_P[cta].M; dc = g_P[cta].c;
            break;
        case 1:
            Ma = g_P[2 * cta].M;     ca = g_P[2 * cta].c;
            Mb = g_P[2 * cta + 1].M; cb = g_P[2 * cta + 1].c;
            dM = g_Q[cta].M; dc = g_Q[cta].c;
            break;
        case 2:
            Ma = g_Q[2 * cta].M;     ca = g_Q[2 * cta].c;
            Mb = g_Q[2 * cta + 1].M; cb = g_Q[2 * cta + 1].c;
            dM = g_R[cta].M; dc = g_R[cta].c;
            break;
        case 3:
            Ma = g_R[0].M; ca = g_R[0].c;
            Mb = g_R[1].M; cb = g_R[1].c;
            dM = g_S.M; dc = g_S.c;
            break;
        default:
            Ma = g_S.M;    ca = g_S.c;
            Mb = g_Q[4].M; cb = g_Q[4].c;
            dM = g_final.M; dc = g_final.c;
            break;
    }
    do_compose(Ma, ca, Mb, cb, dM, dc, sA, sB, scv);
}

// ---------------------------------------------------------------------------
// Apply: out = x @ Mc^T + c. Persistent, 3 CTAs/SM.
// smem: 2x[64][PIT] x-buffers (reused as output stage) + packed B-fragment
// table frag[wc2][kt4][nt4][lane32] (uint4 = {bhi0,bhi1,blo0,blo1}).
// Total dynamic smem = 36864 + 16384 = 53248 B  (3x = 159.7 KB <= 228 KB).
// ---------------------------------------------------------------------------
__global__ void __launch_bounds__(256, 3)
apply_kernel(const float* __restrict__ x, float* __restrict__ out) {
    extern __shared__ float sm[];
    float* xs0 = sm;                          // [64][PIT]
    float* xs1 = sm + TILE_R * PIT;           // [64][PIT]
    uint4* sfrag = reinterpret_cast<uint4*>(sm + 2 * TILE_R * PIT);  // 1024

    const int tid  = threadIdx.x;
    const int lane = tid & 31;
    const int w    = tid >> 5;
    const int g    = lane >> 2;
    const int tig  = lane & 3;
    const int warp_r = (w >> 1) * 16;         // 0,16,32,48
    const int warp_c = (w & 1) * 32;          // 0,32

    const uint32_t xsa0 = smem_u32(xs0);
    const uint32_t xsa1 = smem_u32(xs1);

    // prologue: prefetch first tile
    int t = blockIdx.x;
    if (t < NT) {
        const float* src = x + (size_t)t * TILE_R * DIM;
#pragma unroll
        for (int i = 0; i < 4; i++) {
            int id = tid + i * 256;           // 0..1023
            int row = id >> 4, ch = id & 15;
            CP_ASYNC16(xsa0 + (uint32_t)(row * PIT + ch * 4) * 4, src + id * 4);
        }
        CP_COMMIT();
    }

    // build B-fragment table (warps 0,1) while tile 0 flies
    if (w < 2) {
        const float* Mc = g_final.M;
#pragma unroll
        for (int kt = 0; kt < 4; kt++)
#pragma unroll
            for (int nt = 0; nt < 4; nt++) {
                int n = w * 32 + nt * 8 + g;
                const float* br = Mc + n * DIM + kt * 16 + 2 * tig;
                float2 p0 = *reinterpret_cast<const float2*>(br);
                float2 p1 = *reinterpret_cast<const float2*>(br + 8);
                uint32_t h0, l0, h1, l1;
                split2(p0, h0, l0);
                split2(p1, h1, l1);
                sfrag[((w * 4 + kt) * 4 + nt) * 32 + lane] =
                    make_uint4(h0, h1, l0, l1);
            }
    }

    // bias in regs
    float2 bias[4];
#pragma unroll
    for (int nt = 0; nt < 4; nt++) {
        int col = warp_c + nt * 8 + 2 * tig;
        bias[nt] = *reinterpret_cast<const float2*>(g_final.c + col);
    }
    __syncthreads();   // frag table visible

    const uint4* myfrag = sfrag + ((w & 1) * 4) * 4 * 32 + lane;

    int buf = 0;
    while (t < NT) {
        const int tn = t + GRID_APPLY;
        if (tn < NT) {
            const uint32_t sb = buf ? xsa0 : xsa1;
            const float* src = x + (size_t)tn * TILE_R * DIM;
#pragma unroll
            for (int i = 0; i < 4; i++) {
                int id = tid + i * 256;
                int row = id >> 4, ch = id & 15;
                CP_ASYNC16(sb + (uint32_t)(row * PIT + ch * 4) * 4, src + id * 4);
            }
            CP_COMMIT();
            CP_WAIT(1);
        } else {
            CP_WAIT(0);
        }
        __syncthreads();   // current tile resident

        float* xb = buf ? xs1 : xs0;
        const float* xr  = xb + (size_t)(warp_r + g) * PIT;
        const float* xr8 = xr + 8 * PIT;

        float acc[4][4];
#pragma unroll
        for (int nt = 0; nt < 4; nt++) {
            acc[nt][0] = bias[nt].x; acc[nt][1] = bias[nt].y;
            acc[nt][2] = bias[nt].x; acc[nt][3] = bias[nt].y;
        }

#pragma unroll
        for (int kt = 0; kt < 4; kt++) {
            int kk = kt * 16 + 2 * tig;
            float2 a00 = *reinterpret_cast<const float2*>(xr + kk);
            float2 a10 = *reinterpret_cast<const float2*>(xr8 + kk);
            float2 a01 = *reinterpret_cast<const float2*>(xr + kk + 8);
            float2 a11 = *reinterpret_cast<const float2*>(xr8 + kk + 8);
            uint32_t ahi[4], alo[4];
            split2(a00, ahi[0], alo[0]);
            split2(a10, ahi[1], alo[1]);
            split2(a01, ahi[2], alo[2]);
            split2(a11, ahi[3], alo[3]);
#pragma unroll
            for (int nt = 0; nt < 4; nt++) {
                uint4 f = myfrag[(kt * 4 + nt) * 32];
                mma16816(acc[nt], ahi, f.x, f.y);
                mma16816(acc[nt], ahi, f.z, f.w);
                mma16816(acc[nt], alo, f.x, f.y);
            }
        }

        // stage into the just-consumed buffer (each warp overwrites only the
        // rows it read), then one coalesced STG pass
        float* o0 = xb + (size_t)(warp_r + g) * PIT;
        float* o8 = o0 + 8 * PIT;
#pragma unroll
        for (int nt = 0; nt < 4; nt++) {
            int col = warp_c + nt * 8 + 2 * tig;
            *reinterpret_cast<float2*>(o0 + col) =
                make_float2(acc[nt][0], acc[nt][1]);
            *reinterpret_cast<float2*>(o8 + col) =
                make_float2(acc[nt][2], acc[nt][3]);
        }
        __syncthreads();   // staged tile complete

        float* gdst = out + (size_t)t * TILE_R * DIM;
#pragma unroll
        for (int i = 0; i < 4; i++) {
            int id = tid + i * 256;          // 0..1023
            int row = id >> 4, ch = id & 15;
            float4 v = *reinterpret_cast<const float4*>(xb + row * PIT + ch * 4);
            *reinterpret_cast<float4*>(gdst + id * 4) = v;
        }
        __syncthreads();   // STG reads done before next prefetch reuses xb

        buf ^= 1;
        t = tn;
    }
}

// ---------------------------------------------------------------------------
// Launch
// ---------------------------------------------------------------------------
extern "C" void kernel_launch(void* const* d_in, const int* in_sizes, int n_in,
                              void* d_out, int out_size) {
    const float* x = (const float*)d_in[0];  // [524288, 64]
    const float* W = (const float*)d_in[1];  // [20, 64, 64]
    const float* b = (const float*)d_in[2];  // [20, 64]
    float* out = (float*)d_out;              // [524288, 64]

    const int smem_bytes = (2 * TILE_R * PIT) * (int)sizeof(float) + 16384;
    cudaFuncSetAttribute(apply_kernel,
                         cudaFuncAttributeMaxDynamicSharedMemorySize,
                         smem_bytes);

    compose_level_kernel<<<10, 256>>>(0, W, b);
    compose_level_kernel<<<5,  256>>>(1, W, b);
    compose_level_kernel<<<2,  256>>>(2, W, b);
    compose_level_kernel<<<1,  256>>>(3, W, b);
    compose_level_kernel<<<1,  256>>>(4, W, b);
    apply_kernel<<<GRID_APPLY, 256, smem_bytes>>>(x, out);
}

// round 15
// speedup vs baseline: 1.9470x; 1.0244x over previous
#include <cuda_runtime.h>
#include <cuda_bf16.h>
#include <cstdint>

// ============================================================================
// out = chain of 20 Linear(64,64) over x[524288,64], fp32.
// Affine chain => compose into ONE map (Mc, c): out = x @ Mc^T + c.
//   Compose: TWO launches.
//     Launch 1 (5 CTAs): Q[i] = L(4i+3) o L(4i+2) o L(4i+1) o L(4i)
//                        (3 in-smem composes per CTA, no cross-CTA sync)
//     Launch 2 (1 CTA):  final = Q4 o Q3 o Q2 o Q1 o Q0
//                        (4 sequential in-smem composes)
//   Apply: persistent, 3 CTAs/SM, cp.async double-buffered 64-row tiles,
//          B fragments in packed smem table (LDS.128), coalesced epilogue.
// Base sm_103 target (no tcgen05 in this build pipeline).
// ============================================================================

#define N_TOK   524288
#define DIM     64
#define TILE_R  64
#define NT      (N_TOK / TILE_R)     // 8192 tiles
#define GRID_APPLY 456               // 3 x 152 SMs
#define PIT     72                   // apply smem pitch (floats)
#define PITC    68                   // compose smem pitch (floats)

struct AffineMap {
    float M[DIM * DIM];
    float c[DIM];
};
__device__ AffineMap g_final;
__device__ AffineMap g_Q[5];

// ---------------------------------------------------------------------------
// helpers
// ---------------------------------------------------------------------------
__device__ __forceinline__ void split2(float2 v, uint32_t& hi, uint32_t& lo) {
    __nv_bfloat16 hx = __float2bfloat16_rn(v.x);
    __nv_bfloat16 hy = __float2bfloat16_rn(v.y);
    __nv_bfloat16 lx = __float2bfloat16_rn(v.x - __bfloat162float(hx));
    __nv_bfloat16 ly = __float2bfloat16_rn(v.y - __bfloat162float(hy));
    hi = (uint32_t)__bfloat16_as_ushort(hx) |
         ((uint32_t)__bfloat16_as_ushort(hy) << 16);
    lo = (uint32_t)__bfloat16_as_ushort(lx) |
         ((uint32_t)__bfloat16_as_ushort(ly) << 16);
}

__device__ __forceinline__ void mma16816(float* c, const uint32_t* a,
                                         uint32_t b0, uint32_t b1) {
    asm volatile(
        "mma.sync.aligned.m16n8k16.row.col.f32.bf16.bf16.f32 "
        "{%0,%1,%2,%3}, {%4,%5,%6,%7}, {%8,%9}, {%0,%1,%2,%3};\n"
        : "+f"(c[0]), "+f"(c[1]), "+f"(c[2]), "+f"(c[3])
        : "r"(a[0]), "r"(a[1]), "r"(a[2]), "r"(a[3]), "r"(b0), "r"(b1));
}

__device__ __forceinline__ uint32_t smem_u32(const void* p) {
    uint32_t a;
    asm("{ .reg .u64 t; cvta.to.shared.u64 t, %1; cvt.u32.u64 %0, t; }"
        : "=r"(a) : "l"(p));
    return a;
}

#define CP_ASYNC16(saddr, gptr) \
    asm volatile("cp.async.cg.shared.global [%0], [%1], 16;" \
                 :: "r"(saddr), "l"(gptr))
#define CP_COMMIT() asm volatile("cp.async.commit_group;")
#define CP_WAIT(n)  asm volatile("cp.async.wait_group %0;" :: "n"(n))

// ---------------------------------------------------------------------------
// compose building blocks
// ---------------------------------------------------------------------------
typedef float SmMat[PITC];

// stage one 64x64 fp32 matrix gmem -> smem (pitch PITC) via cp.async
__device__ __forceinline__ void stage_mat(uint32_t sdst,
                                          const float* __restrict__ src,
                                          int tid) {
#pragma unroll
    for (int i = 0; i < 4; i++) {
        int id = tid + i * 256;               // 0..1023
        int row = id >> 4, ch = id & 15;
        CP_ASYNC16(sdst + (uint32_t)(row * PITC + ch * 4) * 4, src + id * 4);
    }
}

// 64x64x64 product into acc regs: D = Bm @ A  (A = applied-first map).
// B-frags from A columns (conflict-free @ PITC=68), A-frags from Bm rows.
// bf16x3 (hh + hl + lh).
__device__ void compose_mat(const SmMat* A, const SmMat* Bm,
                            float acc[4][4], int tid) {
    const int lane = tid & 31;
    const int w    = tid >> 5;
    const int g    = lane >> 2;
    const int tig  = lane & 3;
    const int warp_r = (w >> 1) * 16;
    const int warp_c = (w & 1) * 32;

    uint32_t bhi[4][4][2], blo[4][4][2];
#pragma unroll
    for (int kt = 0; kt < 4; kt++)
#pragma unroll
        for (int nt = 0; nt < 4; nt++) {
            int n  = warp_c + nt * 8 + g;
            int t0 = kt * 16 + 2 * tig;
            float2 p0 = make_float2(A[t0 + 0][n], A[t0 + 1][n]);
            float2 p1 = make_float2(A[t0 + 8][n], A[t0 + 9][n]);
            split2(p0, bhi[kt][nt][0], blo[kt][nt][0]);
            split2(p1, bhi[kt][nt][1], blo[kt][nt][1]);
        }

#pragma unroll
    for (int nt = 0; nt < 4; nt++)
        acc[nt][0] = acc[nt][1] = acc[nt][2] = acc[nt][3] = 0.f;

#pragma unroll
    for (int kt = 0; kt < 4; kt++) {
        int t0 = kt * 16 + 2 * tig;
        const float* ar  = &Bm[warp_r + g][0];
        const float* ar8 = &Bm[warp_r + g + 8][0];
        float2 a00 = make_float2(ar[t0], ar[t0 + 1]);
        float2 a01 = make_float2(ar[t0 + 8], ar[t0 + 9]);
        float2 a10 = make_float2(ar8[t0], ar8[t0 + 1]);
        float2 a11 = make_float2(ar8[t0 + 8], ar8[t0 + 9]);
        uint32_t ahi[4], alo[4];
        split2(a00, ahi[0], alo[0]);
        split2(a10, ahi[1], alo[1]);
        split2(a01, ahi[2], alo[2]);
        split2(a11, ahi[3], alo[3]);
#pragma unroll
        for (int nt = 0; nt < 4; nt++) {
            mma16816(acc[nt], ahi, bhi[kt][nt][0], bhi[kt][nt][1]);
            mma16816(acc[nt], ahi, blo[kt][nt][0], blo[kt][nt][1]);
            mma16816(acc[nt], alo, bhi[kt][nt][0], bhi[kt][nt][1]);
        }
    }
}

// store acc fragments into smem matrix (pitch PITC)
__device__ __forceinline__ void store_acc_smem(SmMat* D, const float acc[4][4],
                                               int tid) {
    const int lane = tid & 31;
    const int w    = tid >> 5;
    const int g    = lane >> 2;
    const int tig  = lane & 3;
    const int warp_r = (w >> 1) * 16;
    const int warp_c = (w & 1) * 32;
#pragma unroll
    for (int nt = 0; nt < 4; nt++) {
        int col = warp_c + nt * 8 + 2 * tig;
        int row = warp_r + g;
        *reinterpret_cast<float2*>(&D[row][col]) =
            make_float2(acc[nt][0], acc[nt][1]);
        *reinterpret_cast<float2*>(&D[row + 8][col]) =
            make_float2(acc[nt][2], acc[nt][3]);
    }
}

// store acc fragments into gmem matrix (pitch DIM)
__device__ __forceinline__ void store_acc_gmem(float* D, const float acc[4][4],
                                               int tid) {
    const int lane = tid & 31;
    const int w    = tid >> 5;
    const int g    = lane >> 2;
    const int tig  = lane & 3;
    const int warp_r = (w >> 1) * 16;
    const int warp_c = (w & 1) * 32;
#pragma unroll
    for (int nt = 0; nt < 4; nt++) {
        int col = warp_c + nt * 8 + 2 * tig;
        int row = warp_r + g;
        *reinterpret_cast<float2*>(D + (size_t)row * DIM + col) =
            make_float2(acc[nt][0], acc[nt][1]);
        *reinterpret_cast<float2*>(D + (size_t)(row + 8) * DIM + col) =
            make_float2(acc[nt][2], acc[nt][3]);
    }
}

// bias: returns cb[j] + dot(Bm[j][:], va[:])  for tid<64 (fp32 exact)
__device__ __forceinline__ float bias_step(const SmMat* Bm, const float* va,
                                           float cbj, int j) {
    float p0 = 0.f, p1 = 0.f;
#pragma unroll
    for (int t = 0; t < DIM; t += 4) {
        float2 w0 = *reinterpret_cast<const float2*>(&Bm[j][t]);
        float2 w1 = *reinterpret_cast<const float2*>(&Bm[j][t + 2]);
        p0 += w0.x * va[t] + w0.y * va[t + 1];
        p1 += w1.x * va[t + 2] + w1.y * va[t + 3];
    }
    return cbj + (p0 + p1);
}

// dynamic smem for compose: 3 matrices + 2 bias vectors
#define CSMEM_BYTES (3 * DIM * PITC * 4 + 2 * DIM * 4)

// ---------------------------------------------------------------------------
// Launch 1: 5 CTAs. CTA i: Q[i] = L(4i+3) o L(4i+2) o L(4i+1) o L(4i)
// ---------------------------------------------------------------------------
__global__ void __launch_bounds__(256)
compose4_kernel(const float* __restrict__ W, const float* __restrict__ bb) {
    extern __shared__ float csm[];
    SmMat* sA = reinterpret_cast<SmMat*>(csm);
    SmMat* sB = reinterpret_cast<SmMat*>(csm + DIM * PITC);
    SmMat* sC = reinterpret_cast<SmMat*>(csm + 2 * DIM * PITC);
    float* vu = csm + 3 * DIM * PITC;       // bias of T1 chain
    float* vw = vu + DIM;                   // bias scratch

    const int tid = threadIdx.x;
    const int L0 = 4 * blockIdx.x;
    float acc[4][4];

    // ---- T1 = L1 o L0 ----
    stage_mat(smem_u32(&sA[0][0]), W + (size_t)L0 * DIM * DIM, tid);
    stage_mat(smem_u32(&sB[0][0]), W + (size_t)(L0 + 1) * DIM * DIM, tid);
    CP_COMMIT();
    if (tid < DIM) vu[tid] = bb[L0 * DIM + tid];          // b0
    CP_WAIT(0);
    __syncthreads();

    compose_mat(sA, sB, acc, tid);
    float br = 0.f;
    if (tid < DIM) br = bias_step(sB, vu, bb[(L0 + 1) * DIM + tid], tid);
    __syncthreads();                    // all reads of sA/sB/vu done
    store_acc_smem(sC, acc, tid);       // T1 -> sC
    if (tid < DIM) vu[tid] = br;        // u = b1 + L1 b0

    // ---- T2 = L3 o L2 ----
    stage_mat(smem_u32(&sA[0][0]), W + (size_t)(L0 + 2) * DIM * DIM, tid);
    stage_mat(smem_u32(&sB[0][0]), W + (size_t)(L0 + 3) * DIM * DIM, tid);
    CP_COMMIT();
    if (tid < DIM) vw[tid] = bb[(L0 + 2) * DIM + tid];    // b2
    CP_WAIT(0);
    __syncthreads();

    compose_mat(sA, sB, acc, tid);
    if (tid < DIM) br = bias_step(sB, vw, bb[(L0 + 3) * DIM + tid], tid);
    __syncthreads();
    store_acc_smem(sA, acc, tid);       // T2 -> sA (reads done)
    if (tid < DIM) vw[tid] = br;        // w = b3 + L3 b2
    __syncthreads();                    // sC, sA, vu, vw all visible

    // ---- Q = T2 o T1 ----
    compose_mat(sC, sA, acc, tid);      // A = T1 (cols), Bm = T2 (rows)
    store_acc_gmem(g_Q[blockIdx.x].M, acc, tid);
    if (tid < DIM)
        g_Q[blockIdx.x].c[tid] = bias_step(sA, vu, vw[tid], tid);
}

// ---------------------------------------------------------------------------
// Launch 2: 1 CTA. final = Q4 o Q3 o Q2 o Q1 o Q0
// ---------------------------------------------------------------------------
__global__ void __launch_bounds__(256)
compose_final_kernel() {
    extern __shared__ float csm[];
    SmMat* sB = reinterpret_cast<SmMat*>(csm + DIM * PITC);
    SmMat* sC = reinterpret_cast<SmMat*>(csm + 2 * DIM * PITC);
    float* vu = csm + 3 * DIM * PITC;

    const int tid = threadIdx.x;
    float acc[4][4];

    // cur = Q0
    stage_mat(smem_u32(&sC[0][0]), g_Q[0].M, tid);
    CP_COMMIT();
    if (tid < DIM) vu[tid] = g_Q[0].c[tid];
    CP_WAIT(0);
    __syncthreads();

#pragma unroll 1
    for (int k = 1; k <= 4; k++) {
        stage_mat(smem_u32(&sB[0][0]), g_Q[k].M, tid);
        CP_COMMIT();
        CP_WAIT(0);
        __syncthreads();                // sB ready; prior sC/vu writes visible

        compose_mat(sC, sB, acc, tid);  // A = cur (cols), Bm = Qk (rows)
        float br = 0.f;
        if (tid < DIM) br = bias_step(sB, vu, g_Q[k].c[tid], tid);
        __syncthreads();                // reads of sC/sB/vu done

        if (k < 4) {
            store_acc_smem(sC, acc, tid);
            if (tid < DIM) vu[tid] = br;
        } else {
            store_acc_gmem(g_final.M, acc, tid);
            if (tid < DIM) g_final.c[tid] = br;
        }
    }
}

// ---------------------------------------------------------------------------
// Apply: out = x @ Mc^T + c. Persistent, 3 CTAs/SM. (unchanged from R14)
// smem: 2x[64][PIT] x-buffers (reused as output stage) + packed B-fragment
// table frag[wc2][kt4][nt4][lane32] (uint4 = {bhi0,bhi1,blo0,blo1}).
// ---------------------------------------------------------------------------
__global__ void __launch_bounds__(256, 3)
apply_kernel(const float* __restrict__ x, float* __restrict__ out) {
    extern __shared__ float sm[];
    float* xs0 = sm;                          // [64][PIT]
    float* xs1 = sm + TILE_R * PIT;           // [64][PIT]
    uint4* sfrag = reinterpret_cast<uint4*>(sm + 2 * TILE_R * PIT);  // 1024

    const int tid  = threadIdx.x;
    const int lane = tid & 31;
    const int w    = tid >> 5;
    const int g    = lane >> 2;
    const int tig  = lane & 3;
    const int warp_r = (w >> 1) * 16;         // 0,16,32,48
    const int warp_c = (w & 1) * 32;          // 0,32

    const uint32_t xsa0 = smem_u32(xs0);
    const uint32_t xsa1 = smem_u32(xs1);

    // prologue: prefetch first tile
    int t = blockIdx.x;
    if (t < NT) {
        const float* src = x + (size_t)t * TILE_R * DIM;
#pragma unroll
        for (int i = 0; i < 4; i++) {
            int id = tid + i * 256;           // 0..1023
            int row = id >> 4, ch = id & 15;
            CP_ASYNC16(xsa0 + (uint32_t)(row * PIT + ch * 4) * 4, src + id * 4);
        }
        CP_COMMIT();
    }

    // build B-fragment table (warps 0,1) while tile 0 flies
    if (w < 2) {
        const float* Mc = g_final.M;
#pragma unroll
        for (int kt = 0; kt < 4; kt++)
#pragma unroll
            for (int nt = 0; nt < 4; nt++) {
                int n = w * 32 + nt * 8 + g;
                const float* br = Mc + n * DIM + kt * 16 + 2 * tig;
                float2 p0 = *reinterpret_cast<const float2*>(br);
                float2 p1 = *reinterpret_cast<const float2*>(br + 8);
                uint32_t h0, l0, h1, l1;
                split2(p0, h0, l0);
                split2(p1, h1, l1);
                sfrag[((w * 4 + kt) * 4 + nt) * 32 + lane] =
                    make_uint4(h0, h1, l0, l1);
            }
    }

    // bias in regs
    float2 bias[4];
#pragma unroll
    for (int nt = 0; nt < 4; nt++) {
        int col = warp_c + nt * 8 + 2 * tig;
        bias[nt] = *reinterpret_cast<const float2*>(g_final.c + col);
    }
    __syncthreads();   // frag table visible

    const uint4* myfrag = sfrag + ((w & 1) * 4) * 4 * 32 + lane;

    int buf = 0;
    while (t < NT) {
        const int tn = t + GRID_APPLY;
        if (tn < NT) {
            const uint32_t sb = buf ? xsa0 : xsa1;
            const float* src = x + (size_t)tn * TILE_R * DIM;
#pragma unroll
            for (int i = 0; i < 4; i++) {
                int id = tid + i * 256;
                int row = id >> 4, ch = id & 15;
                CP_ASYNC16(sb + (uint32_t)(row * PIT + ch * 4) * 4, src + id * 4);
            }
            CP_COMMIT();
            CP_WAIT(1);
        } else {
            CP_WAIT(0);
        }
        __syncthreads();   // current tile resident

        float* xb = buf ? xs1 : xs0;
        const float* xr  = xb + (size_t)(warp_r + g) * PIT;
        const float* xr8 = xr + 8 * PIT;

        float acc[4][4];
#pragma unroll
        for (int nt = 0; nt < 4; nt++) {
            acc[nt][0] = bias[nt].x; acc[nt][1] = bias[nt].y;
            acc[nt][2] = bias[nt].x; acc[nt][3] = bias[nt].y;
        }

#pragma unroll
        for (int kt = 0; kt < 4; kt++) {
            int kk = kt * 16 + 2 * tig;
            float2 a00 = *reinterpret_cast<const float2*>(xr + kk);
            float2 a10 = *reinterpret_cast<const float2*>(xr8 + kk);
            float2 a01 = *reinterpret_cast<const float2*>(xr + kk + 8);
            float2 a11 = *reinterpret_cast<const float2*>(xr8 + kk + 8);
            uint32_t ahi[4], alo[4];
            split2(a00, ahi[0], alo[0]);
            split2(a10, ahi[1], alo[1]);
            split2(a01, ahi[2], alo[2]);
            split2(a11, ahi[3], alo[3]);
#pragma unroll
            for (int nt = 0; nt < 4; nt++) {
                uint4 f = myfrag[(kt * 4 + nt) * 32];
                mma16816(acc[nt], ahi, f.x, f.y);
                mma16816(acc[nt], ahi, f.z, f.w);
                mma16816(acc[nt], alo, f.x, f.y);
            }
        }

        // stage into the just-consumed buffer, then one coalesced STG pass
        float* o0 = xb + (size_t)(warp_r + g) * PIT;
        float* o8 = o0 + 8 * PIT;
#pragma unroll
        for (int nt = 0; nt < 4; nt++) {
            int col = warp_c + nt * 8 + 2 * tig;
            *reinterpret_cast<float2*>(o0 + col) =
                make_float2(acc[nt][0], acc[nt][1]);
            *reinterpret_cast<float2*>(o8 + col) =
                make_float2(acc[nt][2], acc[nt][3]);
        }
        __syncthreads();   // staged tile complete

        float* gdst = out + (size_t)t * TILE_R * DIM;
#pragma unroll
        for (int i = 0; i < 4; i++) {
            int id = tid + i * 256;          // 0..1023
            int row = id >> 4, ch = id & 15;
            float4 v = *reinterpret_cast<const float4*>(xb + row * PIT + ch * 4);
            *reinterpret_cast<float4*>(gdst + id * 4) = v;
        }
        __syncthreads();   // STG reads done before next prefetch reuses xb

        buf ^= 1;
        t = tn;
    }
}

// ---------------------------------------------------------------------------
// Launch
// ---------------------------------------------------------------------------
extern "C" void kernel_launch(void* const* d_in, const int* in_sizes, int n_in,
                              void* d_out, int out_size) {
    const float* x = (const float*)d_in[0];  // [524288, 64]
    const float* W = (const float*)d_in[1];  // [20, 64, 64]
    const float* b = (const float*)d_in[2];  // [20, 64]
    float* out = (float*)d_out;              // [524288, 64]

    const int smem_apply = (2 * TILE_R * PIT) * (int)sizeof(float) + 16384;
    cudaFuncSetAttribute(apply_kernel,
                         cudaFuncAttributeMaxDynamicSharedMemorySize,
                         smem_apply);
    cudaFuncSetAttribute(compose4_kernel,
                         cudaFuncAttributeMaxDynamicSharedMemorySize,
                         CSMEM_BYTES);
    cudaFuncSetAttribute(compose_final_kernel,
                         cudaFuncAttributeMaxDynamicSharedMemorySize,
                         CSMEM_BYTES);

    compose4_kernel<<<5, 256, CSMEM_BYTES>>>(W, b);
    compose_final_kernel<<<1, 256, CSMEM_BYTES>>>();
    apply_kernel<<<GRID_APPLY, 256, smem_apply>>>(x, out);
}